// round 1
// baseline (speedup 1.0000x reference)
#include <cuda_runtime.h>
#include <math.h>

// ---------------- problem constants ----------------
#define DIMC   384
#define HEADS  6
#define HD     64
#define HIDDEN 1536
#define BATCH  4
#define NX     2048
#define NY     256
#define MTOK   2304                 // tokens per batch (NX+NY)
#define TTOK   (BATCH*MTOK)         // 9216 total tokens
#define QKVN   (3*DIMC)             // 1152
#define ATT_SCALE 0.125f            // 64^-0.5
#define LN_EPS 1e-5f

// ---------------- scratch (static device globals; no allocation) ----------------
__device__ float g_catln[TTOK*DIMC];     // LN1 output, concat layout [B,2304,384]
__device__ float g_qkv  [TTOK*QKVN];     // fused qkv   [B,2304,1152]
__device__ float g_attno[TTOK*DIMC];     // attention O (head-merged) [B,2304,384]
__device__ float g_ln2  [TTOK*DIMC];     // LN2 output
__device__ float g_fc1  [TTOK*HIDDEN];   // fc1+gelu output

// ---------------- LayerNorm over 384 channels, 1 token per block ----------------
__global__ void __launch_bounds__(128) ln_kernel(
    const float* __restrict__ px, const float* __restrict__ py,
    const float* __restrict__ w,  const float* __restrict__ bsh,
    float* __restrict__ out)
{
    int t   = blockIdx.x;                  // 0..TTOK-1
    int bb  = t / MTOK;
    int pos = t - bb * MTOK;
    const float* src = (pos < NX)
        ? px + ((size_t)(bb*NX + pos)) * DIMC
        : py + ((size_t)(bb*NY + pos - NX)) * DIMC;

    int tid = threadIdx.x;
    float v0 = src[tid], v1 = src[tid+128], v2 = src[tid+256];
    float s  = v0 + v1 + v2;
    float sq = v0*v0 + v1*v1 + v2*v2;
    #pragma unroll
    for (int o = 16; o; o >>= 1) {
        s  += __shfl_xor_sync(0xffffffffu, s,  o);
        sq += __shfl_xor_sync(0xffffffffu, sq, o);
    }
    __shared__ float sm[4], sm2[4], stat[2];
    int wi = tid >> 5;
    if ((tid & 31) == 0) { sm[wi] = s; sm2[wi] = sq; }
    __syncthreads();
    if (tid == 0) {
        float S = sm[0]+sm[1]+sm[2]+sm[3];
        float Q = sm2[0]+sm2[1]+sm2[2]+sm2[3];
        float mean = S * (1.0f/DIMC);
        float var  = Q * (1.0f/DIMC) - mean*mean;
        stat[0] = mean;
        stat[1] = rsqrtf(var + LN_EPS);
    }
    __syncthreads();
    float mean = stat[0], inv = stat[1];
    float* op = out + (size_t)t * DIMC;
    op[tid]     = (v0-mean)*inv*w[tid]     + bsh[tid];
    op[tid+128] = (v1-mean)*inv*w[tid+128] + bsh[tid+128];
    op[tid+256] = (v2-mean)*inv*w[tid+256] + bsh[tid+256];
}

// ---------------- GEMM: C[M,N] = A[M,K] * W[N,K]^T (+epilogues) ----------------
// EPI 0: plain store (qkv, no bias)
// EPI 1: +bias +input residual (x/y)  -> scatter to out_x/out_y   (proj)
// EPI 2: +bias, exact-erf GELU -> store                            (fc1)
// EPI 3: +bias +current out residual -> out_x/out_y in place       (fc2)
template<int EPI>
__global__ void __launch_bounds__(256) gemm_kernel(
    const float* __restrict__ A, const float* __restrict__ W,
    const float* __restrict__ bias, float* __restrict__ C,
    int M, int N, int K,
    const float* __restrict__ resx, const float* __restrict__ resy,
    float* __restrict__ outx, float* __restrict__ outy)
{
    __shared__ float As[16][68];
    __shared__ float Ws[16][68];
    int tid = threadIdx.x;
    int tx = tid & 15, ty = tid >> 4;
    int m0 = blockIdx.y << 6;
    int n0 = blockIdx.x << 6;
    const float* Ab = A + (size_t)m0 * K;
    const float* Wb = W + (size_t)n0 * K;
    int lr = tid >> 2;            // 0..63 : tile row
    int lc = (tid & 3) << 2;      // 0,4,8,12 : k-col (float4)
    float acc[4][4] = {};

    for (int k0 = 0; k0 < K; k0 += 16) {
        float4 a = *(const float4*)(Ab + (size_t)lr*K + k0 + lc);
        float4 w = *(const float4*)(Wb + (size_t)lr*K + k0 + lc);
        As[lc+0][lr]=a.x; As[lc+1][lr]=a.y; As[lc+2][lr]=a.z; As[lc+3][lr]=a.w;
        Ws[lc+0][lr]=w.x; Ws[lc+1][lr]=w.y; Ws[lc+2][lr]=w.z; Ws[lc+3][lr]=w.w;
        __syncthreads();
        #pragma unroll
        for (int kk = 0; kk < 16; kk++) {
            float4 af = *(const float4*)&As[kk][ty<<2];
            float4 wf = *(const float4*)&Ws[kk][tx<<2];
            acc[0][0]+=af.x*wf.x; acc[0][1]+=af.x*wf.y; acc[0][2]+=af.x*wf.z; acc[0][3]+=af.x*wf.w;
            acc[1][0]+=af.y*wf.x; acc[1][1]+=af.y*wf.y; acc[1][2]+=af.y*wf.z; acc[1][3]+=af.y*wf.w;
            acc[2][0]+=af.z*wf.x; acc[2][1]+=af.z*wf.y; acc[2][2]+=af.z*wf.z; acc[2][3]+=af.z*wf.w;
            acc[3][0]+=af.w*wf.x; acc[3][1]+=af.w*wf.y; acc[3][2]+=af.w*wf.z; acc[3][3]+=af.w*wf.w;
        }
        __syncthreads();
    }

    float bv[4];
    if (EPI != 0) {
        #pragma unroll
        for (int j = 0; j < 4; j++) bv[j] = bias[n0 + (tx<<2) + j];
    }
    #pragma unroll
    for (int i = 0; i < 4; i++) {
        int m = m0 + (ty<<2) + i;
        #pragma unroll
        for (int j = 0; j < 4; j++) {
            int n = n0 + (tx<<2) + j;
            float v = acc[i][j];
            if (EPI == 0) {
                C[(size_t)m*N + n] = v;
            } else if (EPI == 2) {
                v += bv[j];
                C[(size_t)m*N + n] = 0.5f * v * (1.0f + erff(v * 0.70710678118654752f));
            } else {
                int bb  = m / MTOK;
                int pos = m - bb * MTOK;
                float* dst; const float* res;
                if (pos < NX) {
                    size_t idx = ((size_t)(bb*NX + pos))*DIMC + n;
                    dst = outx + idx;
                    res = (EPI == 1) ? (resx + idx) : (outx + idx);
                } else {
                    size_t idx = ((size_t)(bb*NY + pos - NX))*DIMC + n;
                    dst = outy + idx;
                    res = (EPI == 1) ? (resy + idx) : (outy + idx);
                }
                *dst = v + bv[j] + *res;
            }
        }
    }
}

// ---------------- flash-style attention, fp32 ----------------
// 64 queries / block (1 thread = 1 query), K/V tiles of 64 in smem,
// online softmax, O accumulated in registers.
__global__ void __launch_bounds__(64) attn_kernel(
    const float* __restrict__ qkv, float* __restrict__ attno,
    int q_off, int k_len)
{
    __shared__ float Ks[64*64];
    __shared__ float Vs[64*64];
    __shared__ float S [64*64];      // skewed access, conflict-free
    int tid = threadIdx.x;
    int h = blockIdx.y, b = blockIdx.z;
    int qi = q_off + (blockIdx.x << 6) + tid;     // position within batch [0,2304)

    const float* qp = qkv + ((size_t)(b*MTOK + qi))*QKVN + h*HD;
    float4 q4[16];
    #pragma unroll
    for (int i = 0; i < 16; i++) {
        float4 t = *(const float4*)(qp + i*4);
        t.x *= ATT_SCALE; t.y *= ATT_SCALE; t.z *= ATT_SCALE; t.w *= ATT_SCALE;
        q4[i] = t;
    }
    float4 O4[16];
    #pragma unroll
    for (int i = 0; i < 16; i++) O4[i] = make_float4(0.f,0.f,0.f,0.f);
    float m = -INFINITY, l = 0.f;

    const float* kbase = qkv + ((size_t)b*MTOK)*QKVN + DIMC  + h*HD;
    const float* vbase = qkv + ((size_t)b*MTOK)*QKVN + 2*DIMC + h*HD;
    int r0 = tid >> 4;          // 0..3
    int c4 = tid & 15;          // float4 column

    for (int kt = 0; kt < k_len; kt += 64) {
        #pragma unroll
        for (int r = 0; r < 64; r += 4) {
            int row = r + r0;
            const float4* kp = (const float4*)(kbase + (size_t)(kt+row)*QKVN);
            const float4* vp = (const float4*)(vbase + (size_t)(kt+row)*QKVN);
            ((float4*)Ks)[row*16 + c4] = kp[c4];
            ((float4*)Vs)[row*16 + c4] = vp[c4];
        }
        __syncthreads();

        float tmax = m;
        #pragma unroll 4
        for (int j = 0; j < 64; j++) {
            const float4* kr = (const float4*)(Ks + j*64);
            float s = 0.f;
            #pragma unroll
            for (int i = 0; i < 16; i++) {
                float4 k4 = kr[i];
                s += q4[i].x*k4.x + q4[i].y*k4.y + q4[i].z*k4.z + q4[i].w*k4.w;
            }
            S[(tid<<6) + ((j + tid) & 63)] = s;     // skew: bank = (j+tid)%32
            tmax = fmaxf(tmax, s);
        }
        float corr = __expf(m - tmax);
        m = tmax;
        l *= corr;
        #pragma unroll
        for (int i = 0; i < 16; i++) {
            O4[i].x*=corr; O4[i].y*=corr; O4[i].z*=corr; O4[i].w*=corr;
        }
        #pragma unroll
        for (int j = 0; j < 64; j++) {
            int si = (tid<<6) + ((j + tid) & 63);
            float p = __expf(S[si] - m);
            l += p;
            S[si] = p;
        }
        #pragma unroll 2
        for (int j = 0; j < 64; j++) {
            float p = S[(tid<<6) + ((j + tid) & 63)];
            const float4* vr = (const float4*)(Vs + j*64);
            #pragma unroll
            for (int i = 0; i < 16; i++) {
                float4 v4 = vr[i];
                O4[i].x += p*v4.x; O4[i].y += p*v4.y; O4[i].z += p*v4.z; O4[i].w += p*v4.w;
            }
        }
        __syncthreads();
    }

    float inv = 1.f / l;
    float* op = attno + ((size_t)(b*MTOK + qi))*DIMC + h*HD;
    #pragma unroll
    for (int i = 0; i < 16; i++) {
        float4 o = O4[i];
        o.x*=inv; o.y*=inv; o.z*=inv; o.w*=inv;
        *(float4*)(op + i*4) = o;
    }
}

// ---------------- launch ----------------
extern "C" void kernel_launch(void* const* d_in, const int* in_sizes, int n_in,
                              void* d_out, int out_size)
{
    const float* x     = (const float*)d_in[0];
    const float* y     = (const float*)d_in[1];
    const float* n1w   = (const float*)d_in[2];
    const float* n1b   = (const float*)d_in[3];
    const float* n2w   = (const float*)d_in[4];
    const float* n2b   = (const float*)d_in[5];
    const float* qkvw  = (const float*)d_in[6];
    const float* projw = (const float*)d_in[7];
    const float* projb = (const float*)d_in[8];
    const float* fc1w  = (const float*)d_in[9];
    const float* fc1bb = (const float*)d_in[10];
    const float* fc2w  = (const float*)d_in[11];
    const float* fc2b  = (const float*)d_in[12];
    (void)in_sizes; (void)n_in; (void)out_size;

    float* outx = (float*)d_out;
    float* outy = outx + (size_t)BATCH*NX*DIMC;

    float *catln, *qkvb, *attno, *ln2o, *fc1o;
    cudaGetSymbolAddress((void**)&catln, g_catln);
    cudaGetSymbolAddress((void**)&qkvb,  g_qkv);
    cudaGetSymbolAddress((void**)&attno, g_attno);
    cudaGetSymbolAddress((void**)&ln2o,  g_ln2);
    cudaGetSymbolAddress((void**)&fc1o,  g_fc1);

    // 1) LN1 over concat(x, y)
    ln_kernel<<<TTOK, 128>>>(x, y, n1w, n1b, catln);
    // 2) fused QKV GEMM (no bias)
    gemm_kernel<0><<<dim3(QKVN/64, TTOK/64), 256>>>(catln, qkvw, nullptr, qkvb,
        TTOK, QKVN, DIMC, nullptr, nullptr, nullptr, nullptr);
    // 3) x self-attention (queries 0..2048, keys 0..2048)
    attn_kernel<<<dim3(NX/64, HEADS, BATCH), 64>>>(qkvb, attno, 0, NX);
    // 4) y cross-attention (queries 2048..2304, keys 0..2304)
    attn_kernel<<<dim3(NY/64, HEADS, BATCH), 64>>>(qkvb, attno, NX, MTOK);
    // 5) output projection + bias + input residual -> d_out (new_x | new_y)
    gemm_kernel<1><<<dim3(DIMC/64, TTOK/64), 256>>>(attno, projw, projb, nullptr,
        TTOK, DIMC, DIMC, x, y, outx, outy);
    // 6) LN2 over d_out
    ln_kernel<<<TTOK, 128>>>(outx, outy, n2w, n2b, ln2o);
    // 7) fc1 + bias + exact GELU
    gemm_kernel<2><<<dim3(HIDDEN/64, TTOK/64), 256>>>(ln2o, fc1w, fc1bb, fc1o,
        TTOK, HIDDEN, DIMC, nullptr, nullptr, nullptr, nullptr);
    // 8) fc2 + bias + residual (in place on d_out)
    gemm_kernel<3><<<dim3(DIMC/64, TTOK/64), 256>>>(fc1o, fc2w, fc2b, nullptr,
        TTOK, DIMC, HIDDEN, nullptr, nullptr, outx, outy);
}